// round 3
// baseline (speedup 1.0000x reference)
#include <cuda_runtime.h>

#define TLEN 4096
#define BROWS 2048
#define SHIFTW 10
#define NSHIFT 21
#define THREADS 256
#define QUADS_PER_THREAD (TLEN / (THREADS * 4))

__device__ float g_row_mse[BROWS];
__device__ unsigned int g_done = 0;

typedef unsigned long long u64_t;

// packed f32x2 FMA / ADD (Blackwell FFMA2 — only reachable via PTX)
__device__ __forceinline__ void ffma2(float2& d, const float2& a, const float2& b) {
    asm("fma.rn.f32x2 %0, %1, %2, %0;"
        : "+l"(reinterpret_cast<u64_t&>(d))
        : "l"(reinterpret_cast<const u64_t&>(a)),
          "l"(reinterpret_cast<const u64_t&>(b)));
}
__device__ __forceinline__ void fadd2(float2& d, const float2& a) {
    asm("add.rn.f32x2 %0, %1, %0;"
        : "+l"(reinterpret_cast<u64_t&>(d))
        : "l"(reinterpret_cast<const u64_t&>(a)));
}

__global__ __launch_bounds__(THREADS, 2) void shift_loss_kernel(
    const float* __restrict__ x, const float* __restrict__ y,
    float* __restrict__ out)
{
    const int row = blockIdx.x;
    const float* __restrict__ xr = x + (size_t)row * TLEN;
    const float* __restrict__ yr = y + (size_t)row * TLEN;
    const int tid = threadIdx.x;

    __shared__ float red[THREADS / 32][25];
    __shared__ float tot[25];
    __shared__ float corr_sh[NSHIFT];
    __shared__ float mse_sh[NSHIFT];
    __shared__ int is_last_sh;

    float2 acc2[NSHIFT];
#pragma unroll
    for (int s = 0; s < NSHIFT; ++s) acc2[s] = make_float2(0.f, 0.f);
    float2 sx2 = make_float2(0.f, 0.f), sxx2 = sx2, sy2 = sx2, syy2 = sx2;

#pragma unroll
    for (int it = 0; it < QUADS_PER_THREAD; ++it) {
        const int t0 = (it * THREADS + tid) * 4;

        const float4 xv = *reinterpret_cast<const float4*>(xr + t0);
        const float2 X01 = make_float2(xv.x, xv.y);
        const float2 X23 = make_float2(xv.z, xv.w);

        // y window [t0-12, t0+15], zero-padded, as 14 even-aligned pairs E.
        // E[m] = (w[2m], w[2m+1]) where w[i] = y[t0-12+i].
        float2 E[14];
#pragma unroll
        for (int j = 0; j < 7; ++j) {
            const int yb = t0 - 12 + 4 * j;
            if (yb >= 0 && yb + 4 <= TLEN) {
                const float4 v = *reinterpret_cast<const float4*>(yr + yb);
                E[2 * j]     = make_float2(v.x, v.y);
                E[2 * j + 1] = make_float2(v.z, v.w);
            } else {
                float a[4];
#pragma unroll
                for (int k = 0; k < 4; ++k) {
                    const int yi = yb + k;
                    a[k] = (yi >= 0 && yi < TLEN) ? yr[yi] : 0.f;
                }
                E[2 * j]     = make_float2(a[0], a[1]);
                E[2 * j + 1] = make_float2(a[2], a[3]);
            }
        }
        // odd-aligned pairs O[m] = (w[2m+1], w[2m+2]); MOVs land on alu pipe.
        float2 O[12];
#pragma unroll
        for (int m = 1; m <= 11; ++m) O[m] = make_float2(E[m].y, E[m + 1].x);

        // packed row sums (own y quad = w[12..15] = E[6], E[7])
        fadd2(sx2, X01);  fadd2(sx2, X23);
        ffma2(sxx2, X01, X01);  ffma2(sxx2, X23, X23);
        fadd2(sy2, E[6]);  fadd2(sy2, E[7]);
        ffma2(syy2, E[6], E[6]);  ffma2(syy2, E[7], E[7]);

        // acc[s] += sum_k x[t0+k]*w[k+s+2], packed over k-pairs
#pragma unroll
        for (int s = 0; s < NSHIFT; ++s) {
            if ((s & 1) == 0) {
                ffma2(acc2[s], X01, E[(s + 2) >> 1]);
                ffma2(acc2[s], X23, E[(s + 4) >> 1]);
            } else {
                ffma2(acc2[s], X01, O[(s + 1) >> 1]);
                ffma2(acc2[s], X23, O[(s + 3) >> 1]);
            }
        }
    }

    // ---- block reduction of 25 partials ----
    float vals[25];
    vals[0] = sx2.x + sx2.y;  vals[1] = sxx2.x + sxx2.y;
    vals[2] = sy2.x + sy2.y;  vals[3] = syy2.x + syy2.y;
#pragma unroll
    for (int s = 0; s < NSHIFT; ++s) vals[4 + s] = acc2[s].x + acc2[s].y;

#pragma unroll
    for (int i = 0; i < 25; ++i) {
#pragma unroll
        for (int o = 16; o > 0; o >>= 1)
            vals[i] += __shfl_down_sync(0xffffffffu, vals[i], o);
    }
    const int wid = tid >> 5, lane = tid & 31;
    if (lane == 0) {
#pragma unroll
        for (int i = 0; i < 25; ++i) red[wid][i] = vals[i];
    }
    __syncthreads();
    if (tid < 25) {
        float t = 0.f;
#pragma unroll
        for (int wb = 0; wb < THREADS / 32; ++wb) t += red[wb][tid];
        tot[tid] = t;
    }
    __syncthreads();

    // ---- 21 threads: per-shift trimmed Pearson + MSE ----
    if (tid < NSHIFT) {
        const int sh = tid - SHIFTW;
        float Sx = tot[0], Sxx = tot[1], Sy = tot[2], Syy = tot[3];
        const int m = sh < 0 ? -sh : sh;
        const float n = (float)(TLEN - m);
        if (sh > 0) {
            for (int i = 0; i < sh; ++i) {
                const float xv = xr[TLEN - 1 - i]; Sx -= xv; Sxx -= xv * xv;
                const float yv = yr[i];            Sy -= yv; Syy -= yv * yv;
            }
        } else if (sh < 0) {
            for (int i = 0; i < m; ++i) {
                const float xv = xr[i];            Sx -= xv; Sxx -= xv * xv;
                const float yv = yr[TLEN - 1 - i]; Sy -= yv; Syy -= yv * yv;
            }
        }
        const float Sxy = tot[4 + tid];
        const float inv_n = 1.f / n;
        const float cov = Sxy - Sx * Sy * inv_n;
        const float vx  = Sxx - Sx * Sx * inv_n;
        const float vy  = Syy - Sy * Sy * inv_n;
        corr_sh[tid] = cov * rsqrtf(vx * vy);
        mse_sh[tid]  = (Sxx + Syy - 2.f * Sxy) * inv_n;
    }
    __syncthreads();

    if (tid == 0) {
        float best = corr_sh[0];
        int bi = 0;
#pragma unroll
        for (int s = 1; s < NSHIFT; ++s) {
            if (corr_sh[s] > best) { best = corr_sh[s]; bi = s; }  // first-max tie-break
        }
        g_row_mse[row] = mse_sh[bi];
        __threadfence();
        const unsigned int prev = atomicAdd(&g_done, 1u);
        is_last_sh = (prev == BROWS - 1u) ? 1 : 0;
    }
    __syncthreads();

    // ---- last block: fused final mean (deterministic fixed-order sum) ----
    if (is_last_sh) {
        float s = 0.f;
#pragma unroll
        for (int i = 0; i < BROWS / THREADS; ++i)
            s += __ldcg(&g_row_mse[i * THREADS + tid]);
#pragma unroll
        for (int o = 16; o > 0; o >>= 1) s += __shfl_down_sync(0xffffffffu, s, o);
        if (lane == 0) red[wid][0] = s;
        __syncthreads();
        if (tid == 0) {
            float t = 0.f;
#pragma unroll
            for (int wb = 0; wb < THREADS / 32; ++wb) t += red[wb][0];
            out[0] = t / (float)BROWS;
            g_done = 0;  // reset for next graph replay
        }
    }
}

extern "C" void kernel_launch(void* const* d_in, const int* in_sizes, int n_in,
                              void* d_out, int out_size)
{
    const float* x = (const float*)d_in[0];
    const float* y = (const float*)d_in[1];
    shift_loss_kernel<<<BROWS, THREADS>>>(x, y, (float*)d_out);
}

// round 4
// speedup vs baseline: 1.6391x; 1.6391x over previous
#include <cuda_runtime.h>

#define TLEN 4096
#define BROWS 2048
#define SHIFTW 10
#define NSHIFT 21
#define THREADS 256
#define QUADS_PER_THREAD (TLEN / (THREADS * 4))

__device__ float g_row_mse[BROWS];
__device__ unsigned int g_done = 0;

__global__ __launch_bounds__(THREADS, 4) void shift_loss_kernel(
    const float* __restrict__ x, const float* __restrict__ y,
    float* __restrict__ out)
{
    const int row = blockIdx.x;
    const float* __restrict__ xr = x + (size_t)row * TLEN;
    const float* __restrict__ yr = y + (size_t)row * TLEN;
    const int tid = threadIdx.x;

    __shared__ float red[THREADS / 32][25];
    __shared__ float tot[25];
    __shared__ float corr_sh[NSHIFT];
    __shared__ float mse_sh[NSHIFT];
    __shared__ int is_last_sh;

    float acc[NSHIFT];
#pragma unroll
    for (int s = 0; s < NSHIFT; ++s) acc[s] = 0.f;
    float sx = 0.f, sxx = 0.f, sy = 0.f, syy = 0.f;

#pragma unroll
    for (int it = 0; it < QUADS_PER_THREAD; ++it) {
        const int t0 = (it * THREADS + tid) * 4;

        // own x quad (coalesced LDG.128)
        const float4 xv = *reinterpret_cast<const float4*>(xr + t0);
        float xk[4] = {xv.x, xv.y, xv.z, xv.w};
#pragma unroll
        for (int k = 0; k < 4; ++k) { sx += xk[k]; sxx += xk[k] * xk[k]; }

        // Lazy y-window: load one quad at a time, consume immediately.
        // w[i] = y[t0-12+i]; w[i] feeds acc[i-k-2] for k=0..3 when 0<=i-k-2<=20.
#pragma unroll
        for (int j = 0; j < 7; ++j) {
            const int yb = t0 - 12 + 4 * j;
            float w4[4];
            if (yb >= 0 && yb + 4 <= TLEN) {
                const float4 v = *reinterpret_cast<const float4*>(yr + yb);
                w4[0] = v.x; w4[1] = v.y; w4[2] = v.z; w4[3] = v.w;
            } else {
#pragma unroll
                for (int c = 0; c < 4; ++c) {
                    const int yi = yb + c;
                    w4[c] = (yi >= 0 && yi < TLEN) ? yr[yi] : 0.f;
                }
            }
            if (j == 3) {  // own y quad: y[t0..t0+3]
#pragma unroll
                for (int c = 0; c < 4; ++c) { sy += w4[c]; syy += w4[c] * w4[c]; }
            }
#pragma unroll
            for (int c = 0; c < 4; ++c) {
                const int i = 4 * j + c;
#pragma unroll
                for (int k = 0; k < 4; ++k) {
                    const int s = i - k - 2;
                    if (s >= 0 && s < NSHIFT)        // compile-time after unroll
                        acc[s] += xk[k] * w4[c];
                }
            }
        }
    }

    // ---- block reduction of 25 partials ----
    float vals[25];
    vals[0] = sx; vals[1] = sxx; vals[2] = sy; vals[3] = syy;
#pragma unroll
    for (int s = 0; s < NSHIFT; ++s) vals[4 + s] = acc[s];

#pragma unroll
    for (int i = 0; i < 25; ++i) {
#pragma unroll
        for (int o = 16; o > 0; o >>= 1)
            vals[i] += __shfl_down_sync(0xffffffffu, vals[i], o);
    }
    const int wid = tid >> 5, lane = tid & 31;
    if (lane == 0) {
#pragma unroll
        for (int i = 0; i < 25; ++i) red[wid][i] = vals[i];
    }
    __syncthreads();
    if (tid < 25) {
        float t = 0.f;
#pragma unroll
        for (int wb = 0; wb < THREADS / 32; ++wb) t += red[wb][tid];
        tot[tid] = t;
    }
    __syncthreads();

    // ---- 21 threads: per-shift trimmed Pearson + MSE ----
    if (tid < NSHIFT) {
        const int sh = tid - SHIFTW;
        float Sx = tot[0], Sxx = tot[1], Sy = tot[2], Syy = tot[3];
        const int m = sh < 0 ? -sh : sh;
        const float n = (float)(TLEN - m);
        if (sh > 0) {
            for (int i = 0; i < sh; ++i) {
                const float xv = xr[TLEN - 1 - i]; Sx -= xv; Sxx -= xv * xv;
                const float yv = yr[i];            Sy -= yv; Syy -= yv * yv;
            }
        } else if (sh < 0) {
            for (int i = 0; i < m; ++i) {
                const float xv = xr[i];            Sx -= xv; Sxx -= xv * xv;
                const float yv = yr[TLEN - 1 - i]; Sy -= yv; Syy -= yv * yv;
            }
        }
        const float Sxy = tot[4 + tid];
        const float inv_n = 1.f / n;
        const float cov = Sxy - Sx * Sy * inv_n;
        const float vx  = Sxx - Sx * Sx * inv_n;
        const float vy  = Syy - Sy * Sy * inv_n;
        corr_sh[tid] = cov * rsqrtf(vx * vy);
        mse_sh[tid]  = (Sxx + Syy - 2.f * Sxy) * inv_n;
    }
    __syncthreads();

    if (tid == 0) {
        float best = corr_sh[0];
        int bi = 0;
#pragma unroll
        for (int s = 1; s < NSHIFT; ++s) {
            if (corr_sh[s] > best) { best = corr_sh[s]; bi = s; }  // first-max tie-break
        }
        g_row_mse[row] = mse_sh[bi];
        __threadfence();
        const unsigned int prev = atomicAdd(&g_done, 1u);
        is_last_sh = (prev == BROWS - 1u) ? 1 : 0;
    }
    __syncthreads();

    // ---- last block: fused final mean (deterministic fixed-order sum) ----
    if (is_last_sh) {
        float s = 0.f;
#pragma unroll
        for (int i = 0; i < BROWS / THREADS; ++i)
            s += __ldcg(&g_row_mse[i * THREADS + tid]);
#pragma unroll
        for (int o = 16; o > 0; o >>= 1) s += __shfl_down_sync(0xffffffffu, s, o);
        if (lane == 0) red[wid][0] = s;
        __syncthreads();
        if (tid == 0) {
            float t = 0.f;
#pragma unroll
            for (int wb = 0; wb < THREADS / 32; ++wb) t += red[wb][0];
            out[0] = t / (float)BROWS;
            g_done = 0;  // reset for next graph replay
        }
    }
}

extern "C" void kernel_launch(void* const* d_in, const int* in_sizes, int n_in,
                              void* d_out, int out_size)
{
    const float* x = (const float*)d_in[0];
    const float* y = (const float*)d_in[1];
    shift_loss_kernel<<<BROWS, THREADS>>>(x, y, (float*)d_out);
}